// round 9
// baseline (speedup 1.0000x reference)
#include <cuda_runtime.h>
#include <cstdint>

// Per-row nonlinear scan, w[k+1] = w[k] + a/w[k] - b*x[k], 32768 rows x 1024.
// One thread per row; 32x33 smem transpose tiles (pad -> conflict-free).
//
// STRUCTURE = ROUND 2 VERBATIM (best passing: 57.3us ncu). Store-fusion
// regressed twice (R6,R7); restructured pipeline regressed (R4). Don't touch.
//
// MATH: Markstein correctly-rounded divide = R5's sequence VERBATIM
// (R5 measured rel_err 0.0 = bitwise-identical to reference `a / w`),
// with ONE change: seed via __fdividef(1.0f, w) (bare MUFU.RCP through the
// intrinsic path) instead of R5's inline-asm rcp.approx, which dragged
// register copies onto the dependent chain (alu 10.5%, 135 cyc/step).
// R8's failure (rel_err 9e-2) came from altering the TAIL to explicit
// FMUL+FSUB; here the tail is exactly R5's `w = (w + q) - b * xv;`
// which the compiler contracts to FADD + FFMA, matching the reference.
// (Bare rcp.approx without refinement: rel_err 2.05 (R3). Never.)

#define N_COLS 1024
#define WARPS_PER_BLOCK 4
#define TILE 32

// Correctly-rounded a/w (div.rn fast path, Markstein). Bit-proven in R5.
__device__ __forceinline__ float div_fast_rn(float a, float w) {
    float r   = __fdividef(1.0f, w);      // MUFU.RCP seed (intrinsic path)
    float e   = __fmaf_rn(-w, r, 1.0f);   // residual of rcp
    r         = __fmaf_rn(e, r, r);       // refined reciprocal
    float q0  = __fmul_rn(a, r);          // initial quotient
    float rem = __fmaf_rn(-w, q0, a);     // exact remainder (FMA)
    return      __fmaf_rn(rem, r, q0);    // correctly-rounded quotient
}

__global__ __launch_bounds__(WARPS_PER_BLOCK * 32)
void DDK_77644418777662_kernel(const float* __restrict__ x,
                               const float* __restrict__ alpha,
                               const float* __restrict__ beta,
                               float* __restrict__ out,
                               int rows) {
    // one 32x33 tile per warp (disjoint regions -> __syncwarp suffices)
    __shared__ float sh[WARPS_PER_BLOCK][TILE][TILE + 1];

    const int warp = threadIdx.x >> 5;
    const int lane = threadIdx.x & 31;
    const int rowBase = (blockIdx.x * WARPS_PER_BLOCK + warp) * TILE;
    if (rowBase >= rows) return;

    const float a = __ldg(alpha);
    const float b = __ldg(beta);

    const float* xrow = x + (size_t)rowBase * N_COLS;
    float* orow       = out + (size_t)rowBase * N_COLS;

    // cooperative tile indexing: 32 lanes = 4 rows x 8 float4-chunks per pass
    const int tr = lane >> 3;   // 0..3 row offset within 4-row group
    const int tc = lane & 7;    // 0..7 float4 index within row

    float4 pf[8];

    // ---- prologue: load tile 0 into registers, commit to smem ----
    #pragma unroll
    for (int g = 0; g < 8; g++)
        pf[g] = *(const float4*)(xrow + (size_t)(g * 4 + tr) * N_COLS + tc * 4);
    #pragma unroll
    for (int g = 0; g < 8; g++) {
        const int r = g * 4 + tr;
        sh[warp][r][tc * 4 + 0] = pf[g].x;
        sh[warp][r][tc * 4 + 1] = pf[g].y;
        sh[warp][r][tc * 4 + 2] = pf[g].z;
        sh[warp][r][tc * 4 + 3] = pf[g].w;
    }
    __syncwarp();

    float w = 1.0f;

    for (int c0 = 0; c0 < N_COLS; c0 += TILE) {
        const int next = c0 + TILE;

        // ---- issue next tile's loads: 8 independent LDG.128 fly during compute ----
        if (next < N_COLS) {
            #pragma unroll
            for (int g = 0; g < 8; g++)
                pf[g] = *(const float4*)(xrow + (size_t)(g * 4 + tr) * N_COLS
                                         + next + tc * 4);
        }

        // ---- 32 sequential recurrence steps (the dependent chain) ----
        // out[k] = w (pre-update), overwrite smem in place.
        #pragma unroll
        for (int j = 0; j < TILE; j++) {
            const float xv = sh[warp][lane][j];
            sh[warp][lane][j] = w;
            const float q = div_fast_rn(a, w);
            w = (w + q) - b * xv;         // EXACT R5 tail (contracts to FFMA)
        }
        __syncwarp();

        // ---- coalesced store of this tile's outputs ----
        #pragma unroll
        for (int g = 0; g < 8; g++) {
            const int r = g * 4 + tr;
            float4 v;
            v.x = sh[warp][r][tc * 4 + 0];
            v.y = sh[warp][r][tc * 4 + 1];
            v.z = sh[warp][r][tc * 4 + 2];
            v.w = sh[warp][r][tc * 4 + 3];
            *(float4*)(orow + (size_t)r * N_COLS + c0 + tc * 4) = v;
        }
        __syncwarp();

        // ---- commit prefetched registers to smem for the next iteration ----
        if (next < N_COLS) {
            #pragma unroll
            for (int g = 0; g < 8; g++) {
                const int r = g * 4 + tr;
                sh[warp][r][tc * 4 + 0] = pf[g].x;
                sh[warp][r][tc * 4 + 1] = pf[g].y;
                sh[warp][r][tc * 4 + 2] = pf[g].z;
                sh[warp][r][tc * 4 + 3] = pf[g].w;
            }
            __syncwarp();
        }
    }
}

extern "C" void kernel_launch(void* const* d_in, const int* in_sizes, int n_in,
                              void* d_out, int out_size) {
    const float* x     = (const float*)d_in[0];
    const float* alpha = (const float*)d_in[1];
    const float* beta  = (const float*)d_in[2];
    float* out         = (float*)d_out;

    const int rows = out_size / N_COLS;                 // 32768
    const int rowsPerBlock = WARPS_PER_BLOCK * TILE;    // 128
    const int blocks = (rows + rowsPerBlock - 1) / rowsPerBlock;  // 256

    DDK_77644418777662_kernel<<<blocks, WARPS_PER_BLOCK * 32>>>(x, alpha, beta, out, rows);
}

// round 10
// speedup vs baseline: 1.2240x; 1.2240x over previous
#include <cuda_runtime.h>
#include <cstdint>

// Per-row nonlinear scan, w[k+1] = w[k] + a/w[k] - b*x[k], 32768 rows x 1024.
// One thread per row; 32x33 smem transpose tiles (pad -> conflict-free).
//
// STRUCTURE = ROUND 2 (best passing: 57.3us ncu) with ONE change:
// the tile's 32 xv values are pre-loaded from smem into REGISTERS before the
// divide chain. Rationale: the div.rn macro emits FCHK + slow-path branch
// (BSSY/BSYNC) per step; those reconvergence points fence code motion, so
// per-step LDS could not be hoisted and its ~29-cycle latency was serialized
// into the chain (measured ~90 cyc/step vs ~50 theoretical). Register-resident
// xv removes all loads from the chain region. Values and the consuming
// expression are identical -> bitwise-identical output.
//
// ARITHMETIC (FROZEN): w = w + a / w - b * xv;   (rel_err 0.0 in R1/R2/R6/R7)
// Closed lines: rcp.approx (R3: 2.05), manual Markstein div (R5/R9: slower),
// store-fusion into chain (R6/R7: regressed), restructured pipeline (R4).

#define N_COLS 1024
#define WARPS_PER_BLOCK 4
#define TILE 32

__global__ __launch_bounds__(WARPS_PER_BLOCK * 32)
void DDK_77644418777662_kernel(const float* __restrict__ x,
                               const float* __restrict__ alpha,
                               const float* __restrict__ beta,
                               float* __restrict__ out,
                               int rows) {
    // one 32x33 tile per warp (disjoint regions -> __syncwarp suffices)
    __shared__ float sh[WARPS_PER_BLOCK][TILE][TILE + 1];

    const int warp = threadIdx.x >> 5;
    const int lane = threadIdx.x & 31;
    const int rowBase = (blockIdx.x * WARPS_PER_BLOCK + warp) * TILE;
    if (rowBase >= rows) return;

    const float a = __ldg(alpha);
    const float b = __ldg(beta);

    const float* xrow = x + (size_t)rowBase * N_COLS;
    float* orow       = out + (size_t)rowBase * N_COLS;

    // cooperative tile indexing: 32 lanes = 4 rows x 8 float4-chunks per pass
    const int tr = lane >> 3;   // 0..3 row offset within 4-row group
    const int tc = lane & 7;    // 0..7 float4 index within row

    float4 pf[8];

    // ---- prologue: load tile 0 into registers, commit to smem ----
    #pragma unroll
    for (int g = 0; g < 8; g++)
        pf[g] = *(const float4*)(xrow + (size_t)(g * 4 + tr) * N_COLS + tc * 4);
    #pragma unroll
    for (int g = 0; g < 8; g++) {
        const int r = g * 4 + tr;
        sh[warp][r][tc * 4 + 0] = pf[g].x;
        sh[warp][r][tc * 4 + 1] = pf[g].y;
        sh[warp][r][tc * 4 + 2] = pf[g].z;
        sh[warp][r][tc * 4 + 3] = pf[g].w;
    }
    __syncwarp();

    float w = 1.0f;

    for (int c0 = 0; c0 < N_COLS; c0 += TILE) {
        const int next = c0 + TILE;

        // ---- issue next tile's loads: 8 independent LDG.128 fly during compute ----
        if (next < N_COLS) {
            #pragma unroll
            for (int g = 0; g < 8; g++)
                pf[g] = *(const float4*)(xrow + (size_t)(g * 4 + tr) * N_COLS
                                         + next + tc * 4);
        }

        // ---- pre-load this tile's 32 xv into registers (off the chain) ----
        float xv[TILE];
        #pragma unroll
        for (int j = 0; j < TILE; j++)
            xv[j] = sh[warp][lane][j];     // conflict-free: bank=(lane+j)%32

        // ---- 32 sequential recurrence steps: pure-register chain ----
        // out[k] = w (pre-update), overwrite smem in place.
        #pragma unroll
        for (int j = 0; j < TILE; j++) {
            sh[warp][lane][j] = w;
            w = w + a / w - b * xv[j];     // FROZEN expression
        }
        __syncwarp();

        // ---- coalesced store of this tile's outputs ----
        #pragma unroll
        for (int g = 0; g < 8; g++) {
            const int r = g * 4 + tr;
            float4 v;
            v.x = sh[warp][r][tc * 4 + 0];
            v.y = sh[warp][r][tc * 4 + 1];
            v.z = sh[warp][r][tc * 4 + 2];
            v.w = sh[warp][r][tc * 4 + 3];
            *(float4*)(orow + (size_t)r * N_COLS + c0 + tc * 4) = v;
        }
        __syncwarp();

        // ---- commit prefetched registers to smem for the next iteration ----
        if (next < N_COLS) {
            #pragma unroll
            for (int g = 0; g < 8; g++) {
                const int r = g * 4 + tr;
                sh[warp][r][tc * 4 + 0] = pf[g].x;
                sh[warp][r][tc * 4 + 1] = pf[g].y;
                sh[warp][r][tc * 4 + 2] = pf[g].z;
                sh[warp][r][tc * 4 + 3] = pf[g].w;
            }
            __syncwarp();
        }
    }
}

extern "C" void kernel_launch(void* const* d_in, const int* in_sizes, int n_in,
                              void* d_out, int out_size) {
    const float* x     = (const float*)d_in[0];
    const float* alpha = (const float*)d_in[1];
    const float* beta  = (const float*)d_in[2];
    float* out         = (float*)d_out;

    const int rows = out_size / N_COLS;                 // 32768
    const int rowsPerBlock = WARPS_PER_BLOCK * TILE;    // 128
    const int blocks = (rows + rowsPerBlock - 1) / rowsPerBlock;  // 256

    DDK_77644418777662_kernel<<<blocks, WARPS_PER_BLOCK * 32>>>(x, alpha, beta, out, rows);
}

// round 11
// speedup vs baseline: 1.3654x; 1.1156x over previous
#include <cuda_runtime.h>
#include <cstdint>

// Per-row nonlinear scan, w[k+1] = w[k] + a/w[k] - b*x[k], 32768 rows x 1024.
// One thread per row; 32-row x 64-col smem transpose tiles (pad +1).
//
// ARITHMETIC (FROZEN): w = w + a / w - b * xv;  read xv from smem, write w to
// smem, exactly as R1/R2 (rel_err 0.0). Closed lines: rcp.approx (R3: 2.05),
// manual Markstein div (R5/R9: slower), altered tail (R8: 9e-2),
// store-fusion INTO the chain (R6/R7: regressed), xv preload (R10: neutral).
//
// Round 11 = R2 with phase overhead halved+fused:
//  - TILE 32 -> 64: NT 32 -> 16, halving syncwarp/loop/phase fixed costs
//  - store+commit fused: per float4 chunk, LDS output -> STG -> STS next
//    input to the SAME smem address (same-lane same-addr = program order).
//    2 syncwarps per tile instead of 3.
//  - last tile peeled: main loop body is branch-free.

#define N_COLS 1024
#define WPB 4
#define TILE 64
#define ROWS_PER_WARP 32

__global__ __launch_bounds__(WPB * 32)
void DDK_77644418777662_kernel(const float* __restrict__ x,
                               const float* __restrict__ alpha,
                               const float* __restrict__ beta,
                               float* __restrict__ out,
                               int rows) {
    // one 32x65 tile per warp (disjoint regions -> __syncwarp suffices)
    __shared__ float sh[WPB][ROWS_PER_WARP][TILE + 1];

    const int warp = threadIdx.x >> 5;
    const int lane = threadIdx.x & 31;
    const int rowBase = (blockIdx.x * WPB + warp) * ROWS_PER_WARP;
    if (rowBase >= rows) return;

    const float a = __ldg(alpha);
    const float b = __ldg(beta);

    const float* xrow = x + (size_t)rowBase * N_COLS;
    float* orow       = out + (size_t)rowBase * N_COLS;

    // cooperative indexing: 32 lanes = 4 rows x 8 float4-chunks; 2 col-halves
    const int tr = lane >> 3;   // 0..3 row offset within 4-row group
    const int tc = lane & 7;    // 0..7 float4 index within 32-col half

    float4 pf[16];

    // ---- prologue: load tile 0 (32 rows x 64 cols) and commit to smem ----
    #pragma unroll
    for (int g = 0; g < 8; g++)
        #pragma unroll
        for (int h = 0; h < 2; h++)
            pf[g * 2 + h] = *(const float4*)(xrow + (size_t)(g * 4 + tr) * N_COLS
                                             + (tc + 8 * h) * 4);
    #pragma unroll
    for (int g = 0; g < 8; g++) {
        const int r = g * 4 + tr;
        #pragma unroll
        for (int h = 0; h < 2; h++) {
            const int c = (tc + 8 * h) * 4;
            sh[warp][r][c + 0] = pf[g * 2 + h].x;
            sh[warp][r][c + 1] = pf[g * 2 + h].y;
            sh[warp][r][c + 2] = pf[g * 2 + h].z;
            sh[warp][r][c + 3] = pf[g * 2 + h].w;
        }
    }
    __syncwarp();

    float w = 1.0f;

    // ---- main loop: tiles 0..NT-2 (branch-free body) ----
    for (int c0 = 0; c0 < N_COLS - TILE; c0 += TILE) {
        const int next = c0 + TILE;

        // issue next tile's 16 LDG.128 (fly during the ~5800-cycle chain)
        #pragma unroll
        for (int g = 0; g < 8; g++)
            #pragma unroll
            for (int h = 0; h < 2; h++)
                pf[g * 2 + h] = *(const float4*)(xrow + (size_t)(g * 4 + tr) * N_COLS
                                                 + next + (tc + 8 * h) * 4);

        // 64 sequential steps (FROZEN arithmetic, R2's exact smem pattern)
        #pragma unroll
        for (int j = 0; j < TILE; j++) {
            const float xv = sh[warp][lane][j];
            sh[warp][lane][j] = w;
            w = w + a / w - b * xv;
        }
        __syncwarp();

        // fused store + commit: LDS output -> STG -> STS next input (same addr)
        #pragma unroll
        for (int g = 0; g < 8; g++) {
            const int r = g * 4 + tr;
            #pragma unroll
            for (int h = 0; h < 2; h++) {
                const int c = (tc + 8 * h) * 4;
                float4 v;
                v.x = sh[warp][r][c + 0];
                v.y = sh[warp][r][c + 1];
                v.z = sh[warp][r][c + 2];
                v.w = sh[warp][r][c + 3];
                *(float4*)(orow + (size_t)r * N_COLS + c0 + c) = v;
                sh[warp][r][c + 0] = pf[g * 2 + h].x;
                sh[warp][r][c + 1] = pf[g * 2 + h].y;
                sh[warp][r][c + 2] = pf[g * 2 + h].z;
                sh[warp][r][c + 3] = pf[g * 2 + h].w;
            }
        }
        __syncwarp();
    }

    // ---- peeled last tile: chain + store only ----
    {
        const int c0 = N_COLS - TILE;
        #pragma unroll
        for (int j = 0; j < TILE; j++) {
            const float xv = sh[warp][lane][j];
            sh[warp][lane][j] = w;
            w = w + a / w - b * xv;     // final update is dead code (harmless)
        }
        __syncwarp();
        #pragma unroll
        for (int g = 0; g < 8; g++) {
            const int r = g * 4 + tr;
            #pragma unroll
            for (int h = 0; h < 2; h++) {
                const int c = (tc + 8 * h) * 4;
                float4 v;
                v.x = sh[warp][r][c + 0];
                v.y = sh[warp][r][c + 1];
                v.z = sh[warp][r][c + 2];
                v.w = sh[warp][r][c + 3];
                *(float4*)(orow + (size_t)r * N_COLS + c0 + c) = v;
            }
        }
    }
}

extern "C" void kernel_launch(void* const* d_in, const int* in_sizes, int n_in,
                              void* d_out, int out_size) {
    const float* x     = (const float*)d_in[0];
    const float* alpha = (const float*)d_in[1];
    const float* beta  = (const float*)d_in[2];
    float* out         = (float*)d_out;

    const int rows = out_size / N_COLS;                      // 32768
    const int rowsPerBlock = WPB * ROWS_PER_WARP;            // 128
    const int blocks = (rows + rowsPerBlock - 1) / rowsPerBlock;  // 256

    DDK_77644418777662_kernel<<<blocks, WPB * 32>>>(x, alpha, beta, out, rows);
}